// round 3
// baseline (speedup 1.0000x reference)
#include <cuda_runtime.h>

#define N_NODES 50000
#define N_EDGES 800000
#define IN_C    64
#define HID_C   128
#define OUT_C   64

// ---------------- scratch (static device globals; no allocation) ----------------
__device__ __align__(16) float g_S1[N_NODES * IN_C];    // layer-1 neighbor-sum
__device__ __align__(16) float g_H [N_NODES * HID_C];   // layer-1 output (post-relu)
__device__ __align__(16) float g_S2[N_NODES * HID_C];   // layer-2 neighbor-sum
__device__ __align__(16) float g_cnt[N_NODES];          // in-degree (float)
__device__ __align__(16) float g_sea[N_NODES];          // scatter-sum of edge_attr
__device__ __align__(16) int   g_idx[2 * N_EDGES];      // [src(E), dst(E)] as int32
__device__ int g_is64;                                  // edge_index dtype flag

// ---------------- helpers ----------------
__device__ __forceinline__ void red_add_v4(float* p, float4 v) {
    asm volatile("red.global.add.v4.f32 [%0], {%1,%2,%3,%4};"
                 :: "l"(p), "f"(v.x), "f"(v.y), "f"(v.z), "f"(v.w) : "memory");
}

// ---------------- dtype detect + index convert ----------------
// int64 edge ids < 50000 => every odd 32-bit word is 0. int32 random node ids
// => odd words nonzero with overwhelming probability over 128 samples.
__global__ void detect_kernel(const int* __restrict__ ei32) {
    int acc = 0;
    for (int i = 1; i < 256; i += 2) acc |= ei32[i];
    g_is64 = (acc == 0) ? 1 : 0;
}

__global__ void convert_kernel(const void* __restrict__ ei) {
    int e = blockIdx.x * blockDim.x + threadIdx.x;
    if (e >= 2 * N_EDGES) return;
    int v;
    if (g_is64) v = (int)((const long long*)ei)[e];
    else        v = ((const int*)ei)[e];
    g_idx[e] = v;
}

// ---------------- init: S1 = x, cnt = 0, sea = 0 ----------------
__global__ void init_kernel(const float* __restrict__ x) {
    int i = blockIdx.x * blockDim.x + threadIdx.x;
    if (i < N_NODES * IN_C) g_S1[i] = x[i];
    if (i < N_NODES) { g_cnt[i] = 0.0f; g_sea[i] = 0.0f; }
}

// ---------------- edge stats: degree + edge_attr scatter ----------------
__global__ void edge_stats_kernel(const float* __restrict__ ea) {
    int e = blockIdx.x * blockDim.x + threadIdx.x;
    if (e >= N_EDGES) return;
    int d = g_idx[N_EDGES + e];
    atomicAdd(&g_cnt[d], 1.0f);
    atomicAdd(&g_sea[d], ea[e]);
}

// ---------------- edge gather/scatter: S[dst] += feat[src] ----------------
template <int C>
__device__ __forceinline__ void scatter_body(const float* __restrict__ feat,
                                             float* __restrict__ S) {
    const int CH = C / 4;  // float4 chunks per row
    long long t = (long long)blockIdx.x * blockDim.x + threadIdx.x;
    if (t >= (long long)N_EDGES * CH) return;
    int e = (int)(t / CH);
    int c = (int)(t % CH);
    int s = __ldg(&g_idx[e]);
    int d = __ldg(&g_idx[N_EDGES + e]);
    float4 v = reinterpret_cast<const float4*>(feat)[(long long)s * CH + c];
    red_add_v4(reinterpret_cast<float*>(
                   &reinterpret_cast<float4*>(S)[(long long)d * CH + c]), v);
}

__global__ void scatter1_kernel(const float* __restrict__ x) {
    scatter_body<IN_C>(x, g_S1);
}
__global__ void scatter2_kernel() {
    scatter_body<HID_C>(g_H, g_S2);
}

// ---------------- node-level fused linear:
//   out[v][o] = relu( (deg[v]+1)*(x[v]·W[0:C,o] + b[o]) + S[v]·W[C:2C,o] + sea[v]*W[2C,o] )
template <int CIN, int COUT, int NB, int NG, bool RELU, bool WRITE2>
__device__ __forceinline__ void node_body(const float* __restrict__ X,
                                          const float* __restrict__ S,
                                          const float* __restrict__ W,
                                          const float* __restrict__ b,
                                          float* __restrict__ out1,
                                          float* __restrict__ out2) {
    __shared__ float xs[NB][CIN];
    __shared__ float ss[NB][CIN];
    __shared__ float cs[NB], es[NB];
    const int NT = COUT * NG;
    int node0 = blockIdx.x * NB;
    int tid = threadIdx.x;

    const float4* X4 = reinterpret_cast<const float4*>(X) + (long long)node0 * (CIN / 4);
    const float4* S4 = reinterpret_cast<const float4*>(S) + (long long)node0 * (CIN / 4);
    float4* xs4 = reinterpret_cast<float4*>(&xs[0][0]);
    float4* ss4 = reinterpret_cast<float4*>(&ss[0][0]);
    for (int i = tid; i < NB * CIN / 4; i += NT) {
        xs4[i] = X4[i];
        ss4[i] = S4[i];
    }
    if (tid < NB) {
        cs[tid] = g_cnt[node0 + tid] + 1.0f;
        es[tid] = g_sea[node0 + tid];
    }
    __syncthreads();

    int o = tid % COUT;
    int g = tid / COUT;
    const int NPG = NB / NG;

    float accx[NPG], accs[NPG];
#pragma unroll
    for (int n = 0; n < NPG; n++) { accx[n] = 0.0f; accs[n] = 0.0f; }

#pragma unroll 4
    for (int k = 0; k < CIN; k++) {
        float wx = W[k * COUT + o];
        float ws = W[(CIN + k) * COUT + o];
#pragma unroll
        for (int n = 0; n < NPG; n++) {
            int nn = g * NPG + n;
            accx[n] += xs[nn][k] * wx;
            accs[n] += ss[nn][k] * ws;
        }
    }

    float bo = b[o];
    float we = W[2 * CIN * COUT + o];
#pragma unroll
    for (int n = 0; n < NPG; n++) {
        int nn = g * NPG + n;
        float v = cs[nn] * (accx[n] + bo) + accs[n] + es[nn] * we;
        if (RELU) v = fmaxf(v, 0.0f);
        long long idx = (long long)(node0 + nn) * COUT + o;
        out1[idx] = v;
        if (WRITE2) out2[idx] = v;
    }
}

__global__ void __launch_bounds__(128) node1_kernel(const float* __restrict__ x,
                                                    const float* __restrict__ W1,
                                                    const float* __restrict__ b1) {
    node_body<IN_C, HID_C, 16, 1, true, true>(x, g_S1, W1, b1, g_H, g_S2);
}
// NOTE: _mp_layer applies relu INSIDE the layer -> layer-2 output is relu'd
// before log_softmax. RELU=true here (this was the R2 bug).
__global__ void __launch_bounds__(128) node2_kernel(const float* __restrict__ W2,
                                                    const float* __restrict__ b2,
                                                    float* __restrict__ out) {
    node_body<HID_C, OUT_C, 16, 2, true, false>(g_H, g_S2, W2, b2, out, nullptr);
}

// ---------------- log_softmax along the 64-wide rows (one warp per node) --------
__global__ void logsoftmax_kernel(float* __restrict__ out) {
    int warp = (blockIdx.x * blockDim.x + threadIdx.x) >> 5;
    int lane = threadIdx.x & 31;
    if (warp >= N_NODES) return;
    float* row = out + (long long)warp * OUT_C;
    float v0 = row[lane];
    float v1 = row[lane + 32];
    float m = fmaxf(v0, v1);
#pragma unroll
    for (int off = 16; off; off >>= 1) m = fmaxf(m, __shfl_xor_sync(0xffffffffu, m, off));
    float s = __expf(v0 - m) + __expf(v1 - m);
#pragma unroll
    for (int off = 16; off; off >>= 1) s += __shfl_xor_sync(0xffffffffu, s, off);
    float ls = logf(s);
    row[lane] = v0 - m - ls;
    row[lane + 32] = v1 - m - ls;
}

// ---------------- launch ----------------
extern "C" void kernel_launch(void* const* d_in, const int* in_sizes, int n_in,
                              void* d_out, int out_size) {
    // Size-based input binding (all element counts are unique); falls back to
    // positional order for any size that doesn't match.
    const float* x  = (const float*)d_in[0];
    const void*  ei = d_in[1];
    const float* ea = (const float*)d_in[2];
    const float* W1 = (const float*)d_in[3];
    const float* b1 = (const float*)d_in[4];
    const float* W2 = (const float*)d_in[5];
    const float* b2 = (const float*)d_in[6];
    for (int i = 0; i < n_in; i++) {
        switch (in_sizes[i]) {
            case N_NODES * IN_C:            x  = (const float*)d_in[i]; break; // 3,200,000
            case 2 * N_EDGES:               ei = d_in[i];               break; // 1,600,000
            case N_EDGES:                   ea = (const float*)d_in[i]; break; //   800,000
            case (2 * IN_C + 1) * HID_C:    W1 = (const float*)d_in[i]; break; //    16,512
            case HID_C:                     b1 = (const float*)d_in[i]; break; //       128
            case (2 * HID_C + 1) * OUT_C:   W2 = (const float*)d_in[i]; break; //    16,448
            case OUT_C:                     b2 = (const float*)d_in[i]; break; //        64
            default: break;
        }
    }
    float* out = (float*)d_out;

    // 0) dtype detect + index convert (int64 or int32 -> packed int32)
    detect_kernel<<<1, 1>>>((const int*)ei);
    convert_kernel<<<(2 * N_EDGES + 255) / 256, 256>>>(ei);
    // 1) init scratch (S1 = x w/ self-loop, cnt/sea = 0)
    init_kernel<<<(N_NODES * IN_C + 255) / 256, 256>>>(x);
    // 2) degree + edge_attr scatter (shared by both layers)
    edge_stats_kernel<<<(N_EDGES + 255) / 256, 256>>>(ea);
    // 3) layer-1 neighbor gather/scatter: S1[dst] += x[src]
    {
        long long work = (long long)N_EDGES * (IN_C / 4);
        scatter1_kernel<<<(unsigned)((work + 255) / 256), 256>>>(x);
    }
    // 4) layer-1 node linear + relu -> H, and S2 = H (self loop seeded)
    node1_kernel<<<N_NODES / 16, 128>>>(x, W1, b1);
    // 5) layer-2 neighbor gather/scatter: S2[dst] += H[src]
    {
        long long work = (long long)N_EDGES * (HID_C / 4);
        scatter2_kernel<<<(unsigned)((work + 255) / 256), 256>>>();
    }
    // 6) layer-2 node linear + relu -> d_out (pre-softmax)
    node2_kernel<<<N_NODES / 16, 128>>>(W2, b2, out);
    // 7) log_softmax in-place
    logsoftmax_kernel<<<(N_NODES * 32 + 255) / 256, 256>>>(out);
}

// round 8
// speedup vs baseline: 1.0065x; 1.0065x over previous
#include <cuda_runtime.h>

#define N_NODES 50000
#define N_EDGES 800000
#define IN_C    64
#define HID_C   128
#define OUT_C   64

// ---------------- scratch (static device globals; no allocation) ----------------
__device__ __align__(16) float g_S1[N_NODES * IN_C];    // layer-1 neighbor-sum
__device__ __align__(16) float g_H [N_NODES * HID_C];   // layer-1 output (post-relu)
__device__ __align__(16) float g_S2[N_NODES * HID_C];   // layer-2 neighbor-sum
__device__ __align__(16) float g_cnt[N_NODES];          // in-degree (float)
__device__ __align__(16) float g_sea[N_NODES];          // scatter-sum of edge_attr
__device__ __align__(16) int   g_idx[2 * N_EDGES];      // [src(E), dst(E)] as int32
__device__ int g_is64;                                  // edge_index dtype flag

// ---------------- helpers ----------------
__device__ __forceinline__ void red_add_v4(float* p, float4 v) {
    asm volatile("red.global.add.v4.f32 [%0], {%1,%2,%3,%4};"
                 :: "l"(p), "f"(v.x), "f"(v.y), "f"(v.z), "f"(v.w) : "memory");
}

// ---------------- dtype detect + index convert ----------------
__global__ void detect_kernel(const int* __restrict__ ei32) {
    int acc = 0;
    for (int i = 1; i < 256; i += 2) acc |= ei32[i];
    g_is64 = (acc == 0) ? 1 : 0;
}

__global__ void convert_kernel(const void* __restrict__ ei) {
    int e = blockIdx.x * blockDim.x + threadIdx.x;
    if (e >= 2 * N_EDGES) return;
    int v;
    if (g_is64) v = (int)((const long long*)ei)[e];
    else        v = ((const int*)ei)[e];
    g_idx[e] = v;
}

// ---------------- init: S1 = x, cnt = 0, sea = 0 ----------------
__global__ void init_kernel(const float* __restrict__ x) {
    int i = blockIdx.x * blockDim.x + threadIdx.x;
    if (i < N_NODES * IN_C) g_S1[i] = x[i];
    if (i < N_NODES) { g_cnt[i] = 0.0f; g_sea[i] = 0.0f; }
}

// ---------------- edge gather/scatter: S[dst] += feat[src] ----------------
// STATS=true: chunk-0 thread additionally accumulates degree + edge_attr sums
// (absorbs the old edge_stats_kernel launch).
template <int C, bool STATS>
__device__ __forceinline__ void scatter_body(const float* __restrict__ feat,
                                             float* __restrict__ S,
                                             const float* __restrict__ ea) {
    const int CH = C / 4;  // float4 chunks per row
    long long t = (long long)blockIdx.x * blockDim.x + threadIdx.x;
    if (t >= (long long)N_EDGES * CH) return;
    int e = (int)(t / CH);
    int c = (int)(t % CH);
    int s = __ldg(&g_idx[e]);
    int d = __ldg(&g_idx[N_EDGES + e]);
    if (STATS && c == 0) {
        atomicAdd(&g_cnt[d], 1.0f);
        atomicAdd(&g_sea[d], ea[e]);
    }
    float4 v = reinterpret_cast<const float4*>(feat)[(long long)s * CH + c];
    red_add_v4(reinterpret_cast<float*>(
                   &reinterpret_cast<float4*>(S)[(long long)d * CH + c]), v);
}

__global__ void scatter1_kernel(const float* __restrict__ x,
                                const float* __restrict__ ea) {
    scatter_body<IN_C, true>(x, g_S1, ea);
}
__global__ void scatter2_kernel() {
    scatter_body<HID_C, false>(g_H, g_S2, nullptr);
}

// ---------------- node-level fused linear (identical to R3-passing) -------------
//   out[v][o] = relu( (deg[v]+1)*(x[v]·W[0:C,o] + b[o]) + S[v]·W[C:2C,o] + sea[v]*W[2C,o] )
template <int CIN, int COUT, int NB, int NG, bool RELU, bool WRITE2>
__device__ __forceinline__ void node_body(const float* __restrict__ X,
                                          const float* __restrict__ S,
                                          const float* __restrict__ W,
                                          const float* __restrict__ b,
                                          float* __restrict__ out1,
                                          float* __restrict__ out2) {
    __shared__ float xs[NB][CIN];
    __shared__ float ss[NB][CIN];
    __shared__ float cs[NB], es[NB];
    const int NT = COUT * NG;
    int node0 = blockIdx.x * NB;
    int tid = threadIdx.x;

    const float4* X4 = reinterpret_cast<const float4*>(X) + (long long)node0 * (CIN / 4);
    const float4* S4 = reinterpret_cast<const float4*>(S) + (long long)node0 * (CIN / 4);
    float4* xs4 = reinterpret_cast<float4*>(&xs[0][0]);
    float4* ss4 = reinterpret_cast<float4*>(&ss[0][0]);
    for (int i = tid; i < NB * CIN / 4; i += NT) {
        xs4[i] = X4[i];
        ss4[i] = S4[i];
    }
    if (tid < NB) {
        cs[tid] = g_cnt[node0 + tid] + 1.0f;
        es[tid] = g_sea[node0 + tid];
    }
    __syncthreads();

    int o = tid % COUT;
    int g = tid / COUT;
    const int NPG = NB / NG;

    float accx[NPG], accs[NPG];
#pragma unroll
    for (int n = 0; n < NPG; n++) { accx[n] = 0.0f; accs[n] = 0.0f; }

#pragma unroll 4
    for (int k = 0; k < CIN; k++) {
        float wx = W[k * COUT + o];
        float ws = W[(CIN + k) * COUT + o];
#pragma unroll
        for (int n = 0; n < NPG; n++) {
            int nn = g * NPG + n;
            accx[n] += xs[nn][k] * wx;
            accs[n] += ss[nn][k] * ws;
        }
    }

    float bo = b[o];
    float we = W[2 * CIN * COUT + o];
#pragma unroll
    for (int n = 0; n < NPG; n++) {
        int nn = g * NPG + n;
        float v = cs[nn] * (accx[n] + bo) + accs[n] + es[nn] * we;
        if (RELU) v = fmaxf(v, 0.0f);
        long long idx = (long long)(node0 + nn) * COUT + o;
        out1[idx] = v;
        if (WRITE2) out2[idx] = v;
    }
}

__global__ void __launch_bounds__(128) node1_kernel(const float* __restrict__ x,
                                                    const float* __restrict__ W1,
                                                    const float* __restrict__ b1) {
    node_body<IN_C, HID_C, 16, 1, true, true>(x, g_S1, W1, b1, g_H, g_S2);
}
__global__ void __launch_bounds__(128) node2_kernel(const float* __restrict__ W2,
                                                    const float* __restrict__ b2,
                                                    float* __restrict__ out) {
    node_body<HID_C, OUT_C, 16, 2, true, false>(g_H, g_S2, W2, b2, out, nullptr);
}

// ---------------- log_softmax along the 64-wide rows (one warp per node) --------
__global__ void logsoftmax_kernel(float* __restrict__ out) {
    int warp = (blockIdx.x * blockDim.x + threadIdx.x) >> 5;
    int lane = threadIdx.x & 31;
    if (warp >= N_NODES) return;
    float* row = out + (long long)warp * OUT_C;
    float v0 = row[lane];
    float v1 = row[lane + 32];
    float m = fmaxf(v0, v1);
#pragma unroll
    for (int off = 16; off; off >>= 1) m = fmaxf(m, __shfl_xor_sync(0xffffffffu, m, off));
    float s = __expf(v0 - m) + __expf(v1 - m);
#pragma unroll
    for (int off = 16; off; off >>= 1) s += __shfl_xor_sync(0xffffffffu, s, off);
    float ls = logf(s);
    row[lane] = v0 - m - ls;
    row[lane + 32] = v1 - m - ls;
}

// ---------------- launch ----------------
extern "C" void kernel_launch(void* const* d_in, const int* in_sizes, int n_in,
                              void* d_out, int out_size) {
    const float* x  = (const float*)d_in[0];
    const void*  ei = d_in[1];
    const float* ea = (const float*)d_in[2];
    const float* W1 = (const float*)d_in[3];
    const float* b1 = (const float*)d_in[4];
    const float* W2 = (const float*)d_in[5];
    const float* b2 = (const float*)d_in[6];
    for (int i = 0; i < n_in; i++) {
        switch (in_sizes[i]) {
            case N_NODES * IN_C:          x  = (const float*)d_in[i]; break;
            case 2 * N_EDGES:             ei = d_in[i];               break;
            case N_EDGES:                 ea = (const float*)d_in[i]; break;
            case (2 * IN_C + 1) * HID_C:  W1 = (const float*)d_in[i]; break;
            case HID_C:                   b1 = (const float*)d_in[i]; break;
            case (2 * HID_C + 1) * OUT_C: W2 = (const float*)d_in[i]; break;
            case OUT_C:                   b2 = (const float*)d_in[i]; break;
            default: break;
        }
    }
    float* out = (float*)d_out;

    // 0) dtype detect + index convert (int64 or int32 -> packed int32)
    detect_kernel<<<1, 1>>>((const int*)ei);
    convert_kernel<<<(2 * N_EDGES + 255) / 256, 256>>>(ei);
    // 1) init scratch (S1 = x w/ self-loop, cnt/sea = 0)
    init_kernel<<<(N_NODES * IN_C + 255) / 256, 256>>>(x);
    // 2) layer-1 neighbor gather/scatter (+ fused degree/edge_attr stats)
    {
        long long work = (long long)N_EDGES * (IN_C / 4);
        scatter1_kernel<<<(unsigned)((work + 255) / 256), 256>>>(x, ea);
    }
    // 3) layer-1 node linear + relu -> H, and S2 = H (self loop seeded)
    node1_kernel<<<N_NODES / 16, 128>>>(x, W1, b1);
    // 4) layer-2 neighbor gather/scatter: S2[dst] += H[src]
    {
        long long work = (long long)N_EDGES * (HID_C / 4);
        scatter2_kernel<<<(unsigned)((work + 255) / 256), 256>>>();
    }
    // 5) layer-2 node linear + relu -> d_out (pre-softmax)
    node2_kernel<<<N_NODES / 16, 128>>>(W2, b2, out);
    // 6) log_softmax in-place
    logsoftmax_kernel<<<(N_NODES * 32 + 255) / 256, 256>>>(out);
}

// round 9
// speedup vs baseline: 1.0729x; 1.0660x over previous
#include <cuda_runtime.h>

#define N_NODES 50000
#define N_EDGES 800000
#define IN_C    64
#define HID_C   128
#define OUT_C   64

// ---------------- scratch (static device globals; no allocation) ----------------
__device__ __align__(16) float g_S1 [N_NODES * IN_C];   // layer-1 neighbor-sum
__device__ __align__(16) float g_P  [N_NODES * OUT_C];  // H·W2_j  (message proj)
__device__ __align__(16) float g_Q  [N_NODES * OUT_C];  // H·W2_i  (self proj)
__device__ __align__(16) float g_S2p[N_NODES * OUT_C];  // layer-2 proj-aggregate
__device__ __align__(16) float g_cnt[N_NODES];          // in-degree (float)
__device__ __align__(16) float g_sea[N_NODES];          // scatter-sum of edge_attr
__device__ __align__(16) int   g_idx[2 * N_EDGES];      // [src(E), dst(E)] as int32
__device__ int g_is64;                                  // edge_index dtype flag

// ---------------- helpers ----------------
__device__ __forceinline__ void red_add_v4(float* p, float4 v) {
    asm volatile("red.global.add.v4.f32 [%0], {%1,%2,%3,%4};"
                 :: "l"(p), "f"(v.x), "f"(v.y), "f"(v.z), "f"(v.w) : "memory");
}

// ---------------- dtype detect + index convert ----------------
__global__ void detect_kernel(const int* __restrict__ ei32) {
    int acc = 0;
    for (int i = 1; i < 256; i += 2) acc |= ei32[i];
    g_is64 = (acc == 0) ? 1 : 0;
}

__global__ void convert_kernel(const void* __restrict__ ei) {
    int e = blockIdx.x * blockDim.x + threadIdx.x;
    if (e >= 2 * N_EDGES) return;
    int v;
    if (g_is64) v = (int)((const long long*)ei)[e];
    else        v = ((const int*)ei)[e];
    g_idx[e] = v;
}

// ---------------- init: S1 = x, cnt = 0, sea = 0 ----------------
__global__ void init_kernel(const float* __restrict__ x) {
    int i = blockIdx.x * blockDim.x + threadIdx.x;
    if (i < N_NODES * IN_C) g_S1[i] = x[i];
    if (i < N_NODES) { g_cnt[i] = 0.0f; g_sea[i] = 0.0f; }
}

// ---------------- edge gather/scatter: S[dst] += feat[src] (C=64 both layers) ----
template <bool STATS>
__device__ __forceinline__ void scatter_body(const float* __restrict__ feat,
                                             float* __restrict__ S,
                                             const float* __restrict__ ea) {
    const int CH = 16;  // 64 floats / 4
    long long t = (long long)blockIdx.x * blockDim.x + threadIdx.x;
    if (t >= (long long)N_EDGES * CH) return;
    int e = (int)(t / CH);
    int c = (int)(t % CH);
    int s = __ldg(&g_idx[e]);
    int d = __ldg(&g_idx[N_EDGES + e]);
    if (STATS && c == 0) {
        atomicAdd(&g_cnt[d], 1.0f);
        atomicAdd(&g_sea[d], ea[e]);
    }
    float4 v = reinterpret_cast<const float4*>(feat)[(long long)s * CH + c];
    red_add_v4(reinterpret_cast<float*>(
                   &reinterpret_cast<float4*>(S)[(long long)d * CH + c]), v);
}

__global__ void scatter1_kernel(const float* __restrict__ x,
                                const float* __restrict__ ea) {
    scatter_body<true>(x, g_S1, ea);
}
__global__ void scatter2_kernel() {
    scatter_body<false>(g_P, g_S2p, nullptr);
}

// ---------------- node1: layer-1 linear+relu (H in smem), then project by W2 -----
// Stage A (identical math to proven R3/R8 node1, NG=1/128thr/NPG=16):
//   H[v][o] = relu( (deg+1)*(x·W1_i + b1) + S1·W1_j + sea*w1e )   -> smem only
// Stage B: Q[v] = H[v]·W2_i,  P[v] = H[v]·W2_j;  S2p seeded with P (self loop).
__global__ void __launch_bounds__(128) node1_kernel(const float* __restrict__ x,
                                                    const float* __restrict__ W1,
                                                    const float* __restrict__ b1,
                                                    const float* __restrict__ W2) {
    __shared__ float xs[16][IN_C];
    __shared__ float ss[16][IN_C];
    __shared__ float hs[16][HID_C];
    __shared__ float cs[16], es[16];
    int node0 = blockIdx.x * 16;
    int tid = threadIdx.x;

    // cooperative load of 16 node rows (vectorized)
    const float4* X4 = reinterpret_cast<const float4*>(x)    + (long long)node0 * (IN_C / 4);
    const float4* S4 = reinterpret_cast<const float4*>(g_S1) + (long long)node0 * (IN_C / 4);
    float4* xs4 = reinterpret_cast<float4*>(&xs[0][0]);
    float4* ss4 = reinterpret_cast<float4*>(&ss[0][0]);
    for (int i = tid; i < 16 * IN_C / 4; i += 128) {
        xs4[i] = X4[i];
        ss4[i] = S4[i];
    }
    if (tid < 16) {
        cs[tid] = g_cnt[node0 + tid] + 1.0f;
        es[tid] = g_sea[node0 + tid];
    }
    __syncthreads();

    // ---- Stage A: 128 threads = 128 output cols, 16 nodes per thread ----
    {
        int o = tid;
        float accx[16], accs[16];
#pragma unroll
        for (int n = 0; n < 16; n++) { accx[n] = 0.0f; accs[n] = 0.0f; }
#pragma unroll 4
        for (int k = 0; k < IN_C; k++) {
            float wx = W1[k * HID_C + o];
            float ws = W1[(IN_C + k) * HID_C + o];
#pragma unroll
            for (int n = 0; n < 16; n++) {
                accx[n] += xs[n][k] * wx;
                accs[n] += ss[n][k] * ws;
            }
        }
        float bo = b1[o];
        float we = W1[2 * IN_C * HID_C + o];
#pragma unroll
        for (int n = 0; n < 16; n++) {
            float v = cs[n] * (accx[n] + bo) + accs[n] + es[n] * we;
            hs[n][o] = fmaxf(v, 0.0f);
        }
    }
    __syncthreads();

    // ---- Stage B: 128 threads = 64 output cols x 2 node groups (8 nodes each) ---
    {
        int o2 = tid & 63;
        int g2 = tid >> 6;           // 0 or 1
        float accq[8], accp[8];
#pragma unroll
        for (int n = 0; n < 8; n++) { accq[n] = 0.0f; accp[n] = 0.0f; }

        for (int k4 = 0; k4 < HID_C / 4; k4++) {
            int k = k4 * 4;
            float wi0 = W2[(k + 0) * OUT_C + o2];
            float wi1 = W2[(k + 1) * OUT_C + o2];
            float wi2 = W2[(k + 2) * OUT_C + o2];
            float wi3 = W2[(k + 3) * OUT_C + o2];
            float wj0 = W2[(HID_C + k + 0) * OUT_C + o2];
            float wj1 = W2[(HID_C + k + 1) * OUT_C + o2];
            float wj2 = W2[(HID_C + k + 2) * OUT_C + o2];
            float wj3 = W2[(HID_C + k + 3) * OUT_C + o2];
#pragma unroll
            for (int n = 0; n < 8; n++) {
                int nn = g2 * 8 + n;
                float4 h = *reinterpret_cast<const float4*>(&hs[nn][k]);
                accq[n] += h.x * wi0 + h.y * wi1 + h.z * wi2 + h.w * wi3;
                accp[n] += h.x * wj0 + h.y * wj1 + h.z * wj2 + h.w * wj3;
            }
        }
#pragma unroll
        for (int n = 0; n < 8; n++) {
            int nn = g2 * 8 + n;
            long long idx = (long long)(node0 + nn) * OUT_C + o2;
            g_Q[idx] = accq[n];
            g_P[idx] = accp[n];
            g_S2p[idx] = accp[n];   // self-loop seed
        }
    }
}

// ---------------- final: layer-2 elementwise epilogue + log_softmax -------------
//   v[c] = relu( (deg+1)*(Q[c] + b2[c]) + S2p[c] + sea*w2e[c] );  out = log_softmax(v)
__global__ void __launch_bounds__(256) final_kernel(const float* __restrict__ W2,
                                                    const float* __restrict__ b2,
                                                    float* __restrict__ out) {
    int warp = (blockIdx.x * blockDim.x + threadIdx.x) >> 5;
    int lane = threadIdx.x & 31;
    if (warp >= N_NODES) return;
    int v = warp;
    float cnt1 = g_cnt[v] + 1.0f;
    float sea  = g_sea[v];
    long long base = (long long)v * OUT_C;
    const float* w2e = &W2[2 * HID_C * OUT_C];

    float v0 = fmaxf(cnt1 * (g_Q[base + lane]      + b2[lane])      + g_S2p[base + lane]      + sea * w2e[lane],      0.0f);
    float v1 = fmaxf(cnt1 * (g_Q[base + lane + 32] + b2[lane + 32]) + g_S2p[base + lane + 32] + sea * w2e[lane + 32], 0.0f);

    float m = fmaxf(v0, v1);
#pragma unroll
    for (int off = 16; off; off >>= 1) m = fmaxf(m, __shfl_xor_sync(0xffffffffu, m, off));
    float s = __expf(v0 - m) + __expf(v1 - m);
#pragma unroll
    for (int off = 16; off; off >>= 1) s += __shfl_xor_sync(0xffffffffu, s, off);
    float ls = logf(s) + m;
    out[base + lane]      = v0 - ls;
    out[base + lane + 32] = v1 - ls;
}

// ---------------- launch ----------------
extern "C" void kernel_launch(void* const* d_in, const int* in_sizes, int n_in,
                              void* d_out, int out_size) {
    const float* x  = (const float*)d_in[0];
    const void*  ei = d_in[1];
    const float* ea = (const float*)d_in[2];
    const float* W1 = (const float*)d_in[3];
    const float* b1 = (const float*)d_in[4];
    const float* W2 = (const float*)d_in[5];
    const float* b2 = (const float*)d_in[6];
    for (int i = 0; i < n_in; i++) {
        switch (in_sizes[i]) {
            case N_NODES * IN_C:          x  = (const float*)d_in[i]; break;
            case 2 * N_EDGES:             ei = d_in[i];               break;
            case N_EDGES:                 ea = (const float*)d_in[i]; break;
            case (2 * IN_C + 1) * HID_C:  W1 = (const float*)d_in[i]; break;
            case HID_C:                   b1 = (const float*)d_in[i]; break;
            case (2 * HID_C + 1) * OUT_C: W2 = (const float*)d_in[i]; break;
            case OUT_C:                   b2 = (const float*)d_in[i]; break;
            default: break;
        }
    }
    float* out = (float*)d_out;

    // 0) dtype detect + index convert
    detect_kernel<<<1, 1>>>((const int*)ei);
    convert_kernel<<<(2 * N_EDGES + 255) / 256, 256>>>(ei);
    // 1) init scratch (S1 = x w/ self-loop, cnt/sea = 0)
    init_kernel<<<(N_NODES * IN_C + 255) / 256, 256>>>(x);
    // 2) layer-1 neighbor gather/scatter (+ fused degree/edge_attr stats)
    {
        long long work = (long long)N_EDGES * (IN_C / 4);
        scatter1_kernel<<<(unsigned)((work + 255) / 256), 256>>>(x, ea);
    }
    // 3) layer-1 linear + relu (H stays in smem) + W2 projections -> Q, P, S2p seed
    node1_kernel<<<N_NODES / 16, 128>>>(x, W1, b1, W2);
    // 4) layer-2 projected gather/scatter: S2p[dst] += P[src]   (64-wide!)
    {
        long long work = (long long)N_EDGES * (OUT_C / 4);
        scatter2_kernel<<<(unsigned)((work + 255) / 256), 256>>>();
    }
    // 5) layer-2 elementwise epilogue + log_softmax
    final_kernel<<<(N_NODES * 32 + 255) / 256, 256>>>(W2, b2, out);
}

// round 12
// speedup vs baseline: 1.3452x; 1.2538x over previous
#include <cuda_runtime.h>

#define N_NODES 50000
#define N_EDGES 800000
#define IN_C    64
#define HID_C   128
#define OUT_C   64

// ---------------- scratch (static device globals; no allocation) ----------------
__device__ __align__(16) float g_S1 [N_NODES * IN_C];   // layer-1 aggregate (incl self)
__device__ __align__(16) float g_P  [N_NODES * OUT_C];  // H·W2_j  (message proj)
__device__ __align__(16) float g_Q  [N_NODES * OUT_C];  // H·W2_i  (self proj)
__device__ __align__(16) float g_S2p[N_NODES * OUT_C];  // layer-2 proj-aggregate
__device__ __align__(16) float g_cnt[N_NODES];          // in-degree (float)
__device__ __align__(16) float g_sea[N_NODES];          // scatter-sum of edge_attr
__device__ __align__(16) int   g_idx[2 * N_EDGES];      // [src(E), dst(E)] as int32
__device__ int g_is64;                                  // edge_index dtype flag

// ---------------- helpers ----------------
__device__ __forceinline__ void red_add_v4(float* p, float4 v) {
    asm volatile("red.global.add.v4.f32 [%0], {%1,%2,%3,%4};"
                 :: "l"(p), "f"(v.x), "f"(v.y), "f"(v.z), "f"(v.w) : "memory");
}

// ---------------- dtype detect (1 warp, parallel) ----------------
// int64 node ids < 50000 => every odd 32-bit word is 0.
__global__ void detect_kernel(const int* __restrict__ ei32) {
    int lane = threadIdx.x & 31;
    int acc = 0;
#pragma unroll
    for (int j = 0; j < 4; j++) acc |= ei32[2 * (lane + 32 * j) + 1];
#pragma unroll
    for (int off = 16; off; off >>= 1) acc |= __shfl_xor_sync(0xffffffffu, acc, off);
    if (lane == 0) g_is64 = (acc == 0) ? 1 : 0;
}

// ---------------- fused: index convert + S1 = x + cnt/sea = 0 -------------------
__global__ void convert_init_kernel(const void* __restrict__ ei,
                                    const float* __restrict__ x) {
    int i = blockIdx.x * blockDim.x + threadIdx.x;
    if (i < 2 * N_EDGES) {
        int v;
        if (g_is64) v = (int)((const long long*)ei)[i];
        else        v = ((const int*)ei)[i];
        g_idx[i] = v;
    }
    if (i < N_NODES * IN_C) g_S1[i] = x[i];
    if (i < N_NODES) { g_cnt[i] = 0.0f; g_sea[i] = 0.0f; }
}

// ---------------- edge gather/scatter: S[dst] += feat[src] (C=64 both layers) ----
template <bool STATS>
__device__ __forceinline__ void scatter_body(const float* __restrict__ feat,
                                             float* __restrict__ S,
                                             const float* __restrict__ ea) {
    const int CH = 16;  // 64 floats / 4
    long long t = (long long)blockIdx.x * blockDim.x + threadIdx.x;
    if (t >= (long long)N_EDGES * CH) return;
    int e = (int)(t / CH);
    int c = (int)(t % CH);
    int s = __ldg(&g_idx[e]);
    int d = __ldg(&g_idx[N_EDGES + e]);
    if (STATS && c == 0) {
        atomicAdd(&g_cnt[d], 1.0f);
        atomicAdd(&g_sea[d], ea[e]);
    }
    float4 v = reinterpret_cast<const float4*>(feat)[(long long)s * CH + c];
    red_add_v4(reinterpret_cast<float*>(
                   &reinterpret_cast<float4*>(S)[(long long)d * CH + c]), v);
}

__global__ void scatter1_kernel(const float* __restrict__ x,
                                const float* __restrict__ ea) {
    scatter_body<true>(x, g_S1, ea);
}
__global__ void scatter2_kernel() {
    scatter_body<false>(g_P, g_S2p, nullptr);
}

// ---------------- node1: layer-1 linear+relu (H in smem), then project by W2 -----
__global__ void __launch_bounds__(128) node1_kernel(const float* __restrict__ x,
                                                    const float* __restrict__ W1,
                                                    const float* __restrict__ b1,
                                                    const float* __restrict__ W2) {
    __shared__ float xs[16][IN_C];
    __shared__ float ss[16][IN_C];
    __shared__ float hs[16][HID_C];
    __shared__ float cs[16], es[16];
    int node0 = blockIdx.x * 16;
    int tid = threadIdx.x;

    const float4* X4 = reinterpret_cast<const float4*>(x)    + (long long)node0 * (IN_C / 4);
    const float4* S4 = reinterpret_cast<const float4*>(g_S1) + (long long)node0 * (IN_C / 4);
    float4* xs4 = reinterpret_cast<float4*>(&xs[0][0]);
    float4* ss4 = reinterpret_cast<float4*>(&ss[0][0]);
    for (int i = tid; i < 16 * IN_C / 4; i += 128) {
        xs4[i] = X4[i];
        ss4[i] = S4[i];
    }
    if (tid < 16) {
        cs[tid] = g_cnt[node0 + tid] + 1.0f;
        es[tid] = g_sea[node0 + tid];
    }
    __syncthreads();

    // ---- Stage A: 128 threads = 128 output cols, 16 nodes per thread ----
    // float4 smem reads over k: 4x fewer LDS instructions than scalar version.
    {
        int o = tid;
        float accx[16], accs[16];
#pragma unroll
        for (int n = 0; n < 16; n++) { accx[n] = 0.0f; accs[n] = 0.0f; }

        for (int k4 = 0; k4 < IN_C / 4; k4++) {
            int k = k4 * 4;
            float wx0 = W1[(k + 0) * HID_C + o];
            float wx1 = W1[(k + 1) * HID_C + o];
            float wx2 = W1[(k + 2) * HID_C + o];
            float wx3 = W1[(k + 3) * HID_C + o];
            float ws0 = W1[(IN_C + k + 0) * HID_C + o];
            float ws1 = W1[(IN_C + k + 1) * HID_C + o];
            float ws2 = W1[(IN_C + k + 2) * HID_C + o];
            float ws3 = W1[(IN_C + k + 3) * HID_C + o];
#pragma unroll
            for (int n = 0; n < 16; n++) {
                float4 xv = *reinterpret_cast<const float4*>(&xs[n][k]);
                float4 sv = *reinterpret_cast<const float4*>(&ss[n][k]);
                accx[n] += xv.x * wx0 + xv.y * wx1 + xv.z * wx2 + xv.w * wx3;
                accs[n] += sv.x * ws0 + sv.y * ws1 + sv.z * ws2 + sv.w * ws3;
            }
        }
        float bo = b1[o];
        float we = W1[2 * IN_C * HID_C + o];
#pragma unroll
        for (int n = 0; n < 16; n++) {
            float v = cs[n] * (accx[n] + bo) + accs[n] + es[n] * we;
            hs[n][o] = fmaxf(v, 0.0f);
        }
    }
    __syncthreads();

    // ---- Stage B: Q = H·W2_i, P = H·W2_j  (64 cols x 2 node groups of 8) ----
    {
        int o2 = tid & 63;
        int g2 = tid >> 6;
        float accq[8], accp[8];
#pragma unroll
        for (int n = 0; n < 8; n++) { accq[n] = 0.0f; accp[n] = 0.0f; }

        for (int k4 = 0; k4 < HID_C / 4; k4++) {
            int k = k4 * 4;
            float wi0 = W2[(k + 0) * OUT_C + o2];
            float wi1 = W2[(k + 1) * OUT_C + o2];
            float wi2 = W2[(k + 2) * OUT_C + o2];
            float wi3 = W2[(k + 3) * OUT_C + o2];
            float wj0 = W2[(HID_C + k + 0) * OUT_C + o2];
            float wj1 = W2[(HID_C + k + 1) * OUT_C + o2];
            float wj2 = W2[(HID_C + k + 2) * OUT_C + o2];
            float wj3 = W2[(HID_C + k + 3) * OUT_C + o2];
#pragma unroll
            for (int n = 0; n < 8; n++) {
                int nn = g2 * 8 + n;
                float4 h = *reinterpret_cast<const float4*>(&hs[nn][k]);
                accq[n] += h.x * wi0 + h.y * wi1 + h.z * wi2 + h.w * wi3;
                accp[n] += h.x * wj0 + h.y * wj1 + h.z * wj2 + h.w * wj3;
            }
        }
#pragma unroll
        for (int n = 0; n < 8; n++) {
            int nn = g2 * 8 + n;
            long long idx = (long long)(node0 + nn) * OUT_C + o2;
            g_Q[idx] = accq[n];
            g_P[idx] = accp[n];
            g_S2p[idx] = accp[n];   // self-loop seed
        }
    }
}

// ---------------- final: layer-2 elementwise epilogue + log_softmax -------------
__global__ void __launch_bounds__(256) final_kernel(const float* __restrict__ W2,
                                                    const float* __restrict__ b2,
                                                    float* __restrict__ out) {
    int warp = (blockIdx.x * blockDim.x + threadIdx.x) >> 5;
    int lane = threadIdx.x & 31;
    if (warp >= N_NODES) return;
    int v = warp;
    float cnt1 = g_cnt[v] + 1.0f;
    float sea  = g_sea[v];
    long long base = (long long)v * OUT_C;
    const float* w2e = &W2[2 * HID_C * OUT_C];

    float v0 = fmaxf(cnt1 * (g_Q[base + lane]      + b2[lane])      + g_S2p[base + lane]      + sea * w2e[lane],      0.0f);
    float v1 = fmaxf(cnt1 * (g_Q[base + lane + 32] + b2[lane + 32]) + g_S2p[base + lane + 32] + sea * w2e[lane + 32], 0.0f);

    float m = fmaxf(v0, v1);
#pragma unroll
    for (int off = 16; off; off >>= 1) m = fmaxf(m, __shfl_xor_sync(0xffffffffu, m, off));
    float s = __expf(v0 - m) + __expf(v1 - m);
#pragma unroll
    for (int off = 16; off; off >>= 1) s += __shfl_xor_sync(0xffffffffu, s, off);
    float ls = logf(s) + m;
    out[base + lane]      = v0 - ls;
    out[base + lane + 32] = v1 - ls;
}

// ---------------- launch ----------------
extern "C" void kernel_launch(void* const* d_in, const int* in_sizes, int n_in,
                              void* d_out, int out_size) {
    const float* x  = (const float*)d_in[0];
    const void*  ei = d_in[1];
    const float* ea = (const float*)d_in[2];
    const float* W1 = (const float*)d_in[3];
    const float* b1 = (const float*)d_in[4];
    const float* W2 = (const float*)d_in[5];
    const float* b2 = (const float*)d_in[6];
    for (int i = 0; i < n_in; i++) {
        switch (in_sizes[i]) {
            case N_NODES * IN_C:          x  = (const float*)d_in[i]; break;
            case 2 * N_EDGES:             ei = d_in[i];               break;
            case N_EDGES:                 ea = (const float*)d_in[i]; break;
            case (2 * IN_C + 1) * HID_C:  W1 = (const float*)d_in[i]; break;
            case HID_C:                   b1 = (const float*)d_in[i]; break;
            case (2 * HID_C + 1) * OUT_C: W2 = (const float*)d_in[i]; break;
            case OUT_C:                   b2 = (const float*)d_in[i]; break;
            default: break;
        }
    }
    float* out = (float*)d_out;

    // 0) dtype detect (parallel); fused convert + init
    detect_kernel<<<1, 32>>>((const int*)ei);
    convert_init_kernel<<<(N_NODES * IN_C + 255) / 256, 256>>>(ei, x);
    // 1) layer-1 neighbor gather/scatter (+ fused degree/edge_attr stats)
    {
        long long work = (long long)N_EDGES * (IN_C / 4);
        scatter1_kernel<<<(unsigned)((work + 255) / 256), 256>>>(x, ea);
    }
    // 2) layer-1 linear + relu (H in smem) + W2 projections -> Q, P, S2p seed
    node1_kernel<<<N_NODES / 16, 128>>>(x, W1, b1, W2);
    // 3) layer-2 projected gather/scatter: S2p[dst] += P[src]   (64-wide)
    {
        long long work = (long long)N_EDGES * (OUT_C / 4);
        scatter2_kernel<<<(unsigned)((work + 255) / 256), 256>>>();
    }
    // 4) layer-2 elementwise epilogue + log_softmax
    final_kernel<<<(N_NODES * 32 + 255) / 256, 256>>>(W2, b2, out);
}